// round 3
// baseline (speedup 1.0000x reference)
#include <cuda_runtime.h>
#include <cuda_bf16.h>
#include <cstdint>

// Problem constants (fixed shapes)
#define L_TOK   4096
#define D_HID   768
#define H_HEAD  12
#define DH      64
#define M2      2048          // L/2
#define R_MERGE 2047          // src rows 1..2047 merged
#define OUT_TOK 2049          // 1 unmerged + 2048 dst

// ---------------- device scratch (no allocations allowed) ----------------
__device__ float              g_m[L_TOK * DH];      // normalized metric, 1 MB
__device__ unsigned long long g_best[M2];           // packed (score, ~col)
__device__ int                g_cnt[M2];            // #srcs per dst
__device__ int                g_dst[M2];            // dst index per src row
__device__ float              g_inv[M2];            // 1/(1+cnt)

__device__ __forceinline__ unsigned sortable_f32(float f) {
    unsigned u = __float_as_uint(f);
    return (u & 0x80000000u) ? ~u : (u | 0x80000000u);
}

// ------------------------------------------------------------------------
// K1: metric = mean over heads of key_layer[0], L2-normalized per row.
//     Also initializes g_best / g_cnt.
// grid: 512 blocks x 256 threads (one warp per row)
// ------------------------------------------------------------------------
__global__ void k_metric(const float* __restrict__ key) {
    int gtid = blockIdx.x * blockDim.x + threadIdx.x;
    if (gtid < M2) { g_best[gtid] = 0ull; g_cnt[gtid] = 0; }

    int row  = gtid >> 5;                 // one warp per row
    int lane = threadIdx.x & 31;
    if (row < L_TOK) {
        float v0 = 0.f, v1 = 0.f;
        const float* base = key + (size_t)row * DH;
        #pragma unroll
        for (int h = 0; h < H_HEAD; h++) {
            v0 += base[(size_t)h * L_TOK * DH + lane];
            v1 += base[(size_t)h * L_TOK * DH + lane + 32];
        }
        const float invH = 1.0f / (float)H_HEAD;
        v0 *= invH; v1 *= invH;
        float ss = v0 * v0 + v1 * v1;
        #pragma unroll
        for (int o = 16; o; o >>= 1) ss += __shfl_xor_sync(0xffffffffu, ss, o);
        float r = rsqrtf(ss);
        r = r * (1.5f - 0.5f * ss * r * r);   // one Newton step
        g_m[row * DH + lane]      = v0 * r;
        g_m[row * DH + lane + 32] = v1 * r;
    }
}

// ------------------------------------------------------------------------
// K2: for every a-row i (even rows of m), argmax over b-rows j (odd rows)
//     of dot(a_i, b_j).  2048 x 2048 x 64 fp32 GEMM + argmax epilogue.
// Tile 64x64, 256 threads, 4x4 microtile, single K pass (K = 64).
// grid: (32, 32)
// ------------------------------------------------------------------------
#define TS 64
#define SSTR 68    // smem row stride in floats: 68*4 = 272 B, 16B aligned
__global__ __launch_bounds__(256) void k_argmax() {
    __shared__ float As[TS * SSTR];   // K-major: As[k*SSTR + m]
    __shared__ float Bs[TS * SSTR];

    int tid = threadIdx.x;
    int tx  = tid & 15;               // n direction, 0..15
    int ty  = tid >> 4;               // m direction, 0..15

    int aRow0 = blockIdx.y * TS;      // a-row tile base (in 0..2047)
    int bRow0 = blockIdx.x * TS;      // b-row tile base

    // Load tiles (transpose to K-major). lane-major over m keeps STS conflict-free.
    int lm = tid & 15;                // m within 16-row group
    int kq = tid >> 4;                // which float4 along K, 0..15
    #pragma unroll
    for (int it = 0; it < 4; it++) {
        int m = it * 16 + lm;
        float4 va = *(const float4*)&g_m[(size_t)(2 * (aRow0 + m)) * DH + kq * 4];
        float4 vb = *(const float4*)&g_m[(size_t)(2 * (bRow0 + m) + 1) * DH + kq * 4];
        As[(kq * 4 + 0) * SSTR + m] = va.x;
        As[(kq * 4 + 1) * SSTR + m] = va.y;
        As[(kq * 4 + 2) * SSTR + m] = va.z;
        As[(kq * 4 + 3) * SSTR + m] = va.w;
        Bs[(kq * 4 + 0) * SSTR + m] = vb.x;
        Bs[(kq * 4 + 1) * SSTR + m] = vb.y;
        Bs[(kq * 4 + 2) * SSTR + m] = vb.z;
        Bs[(kq * 4 + 3) * SSTR + m] = vb.w;
    }
    __syncthreads();

    float acc[4][4];
    #pragma unroll
    for (int r = 0; r < 4; r++)
        #pragma unroll
        for (int c = 0; c < 4; c++) acc[r][c] = 0.f;

    #pragma unroll 16
    for (int k = 0; k < TS; k++) {
        float4 av = *(const float4*)&As[k * SSTR + ty * 4];
        float4 bv = *(const float4*)&Bs[k * SSTR + tx * 4];
        float a[4] = {av.x, av.y, av.z, av.w};
        float b[4] = {bv.x, bv.y, bv.z, bv.w};
        #pragma unroll
        for (int r = 0; r < 4; r++)
            #pragma unroll
            for (int c = 0; c < 4; c++)
                acc[r][c] = fmaf(a[r], b[c], acc[r][c]);
    }

    // Argmax epilogue: per a-row, reduce across the 16 threads (one half-warp)
    #pragma unroll
    for (int r = 0; r < 4; r++) {
        int row = aRow0 + ty * 4 + r;
        unsigned long long key = 0ull;
        #pragma unroll
        for (int c = 0; c < 4; c++) {
            int col = bRow0 + tx * 4 + c;
            unsigned long long k2 =
                ((unsigned long long)sortable_f32(acc[r][c]) << 32) |
                (unsigned)(~(unsigned)col);   // smaller col wins ties
            key = (k2 > key) ? k2 : key;
        }
        #pragma unroll
        for (int o = 8; o; o >>= 1) {
            unsigned long long other = __shfl_down_sync(0xffffffffu, key, o, 16);
            key = (other > key) ? other : key;
        }
        if (tx == 0) atomicMax(&g_best[row], key);
    }
}

// ------------------------------------------------------------------------
// K3: extract dst indices + counts.  grid: 8 x 256
// ------------------------------------------------------------------------
__global__ void k_extract() {
    int i = blockIdx.x * blockDim.x + threadIdx.x;
    if (i < M2) {
        int j = (int)(~(unsigned)g_best[i]) & (M2 - 1);  // recover col (clamped)
        g_dst[i] = j;
        if (i >= 1) atomicAdd(&g_cnt[j], 1);
    }
}

// ------------------------------------------------------------------------
// K4: init output: dst rows pre-scaled by 1/cnt, row0 copy, mask zeros,
//     tome init.  grid: 2049 blocks x 192 threads (768 floats = 192 float4)
// ------------------------------------------------------------------------
__global__ void k_prep(const float* __restrict__ hidden,
                       const float* __restrict__ tome,
                       float* __restrict__ out) {
    float* out_tok  = out;                              // 2049 x 768
    float* out_mask = out + (size_t)OUT_TOK * D_HID;    // 2049
    float* out_tome = out_mask + OUT_TOK;               // 2049
    int b = blockIdx.x, t = threadIdx.x;

    if (b < M2) {
        int j = b;
        float inv = 1.0f / (1.0f + (float)g_cnt[j]);
        if (t == 0) {
            g_inv[j] = inv;
            out_tome[1 + j] = tome[2 * j + 1];
        }
        float4 v = ((const float4*)&hidden[(size_t)(2 * j + 1) * D_HID])[t];
        v.x *= inv; v.y *= inv; v.z *= inv; v.w *= inv;
        ((float4*)&out_tok[(size_t)(1 + j) * D_HID])[t] = v;
    } else {
        // b == 2048: unmerged row 0 (src row 0 = hidden row 0), mask, tome[0]
        ((float4*)out_tok)[t] = ((const float4*)hidden)[t];
        for (int i = t; i < OUT_TOK; i += 192) out_mask[i] = 0.0f;
        if (t == 0) out_tome[0] = tome[0];
    }
}

// ------------------------------------------------------------------------
// K5: scatter-add src rows (pre-scaled) into their dst output rows.
// grid: 2047 blocks x 192 threads
// ------------------------------------------------------------------------
__global__ void k_scatter(const float* __restrict__ hidden,
                          const float* __restrict__ tome,
                          float* __restrict__ out) {
    float* out_tok  = out;
    float* out_tome = out + (size_t)OUT_TOK * D_HID + OUT_TOK;
    int i = 1 + blockIdx.x;        // src rows 1..2047
    int t = threadIdx.x;
    int j = g_dst[i];
    float inv = g_inv[j];

    float4 v = ((const float4*)&hidden[(size_t)(2 * i) * D_HID])[t];
    float* d = &out_tok[(size_t)(1 + j) * D_HID + t * 4];
    atomicAdd(d + 0, v.x * inv);
    atomicAdd(d + 1, v.y * inv);
    atomicAdd(d + 2, v.z * inv);
    atomicAdd(d + 3, v.w * inv);
    if (t == 0) atomicAdd(&out_tome[1 + j], tome[2 * i]);
}

// ------------------------------------------------------------------------
extern "C" void kernel_launch(void* const* d_in, const int* in_sizes, int n_in,
                              void* d_out, int out_size) {
    // inputs (metadata order): hidden_states, attention_mask,
    //                          self_attention_scores, key_layer, tome_size
    const float* hidden = (const float*)d_in[0];
    const float* key    = (const float*)d_in[3];
    const float* tome   = (const float*)d_in[4];
    float* out = (float*)d_out;

    k_metric<<<512, 256>>>(key);
    k_argmax<<<dim3(M2 / TS, M2 / TS), 256>>>();
    k_extract<<<8, 256>>>();
    k_prep<<<OUT_TOK, 192>>>(hidden, tome, out);
    k_scatter<<<R_MERGE, 192>>>(hidden, tome, out);
}

// round 4
// speedup vs baseline: 1.0587x; 1.0587x over previous
#include <cuda_runtime.h>
#include <cuda_bf16.h>
#include <cstdint>

// Problem constants (fixed shapes)
#define L_TOK   4096
#define D_HID   768
#define H_HEAD  12
#define DH      64
#define M2      2048          // L/2
#define R_MERGE 2047          // src rows 1..2047 merged
#define OUT_TOK 2049          // 1 unmerged + 2048 dst

// ---------------- device scratch (no allocations allowed) ----------------
__device__ float              g_m[L_TOK * DH];      // normalized metric, 1 MB
__device__ unsigned long long g_best[M2];           // packed (score, ~col)
__device__ int                g_cnt[M2];            // #srcs per dst
__device__ int                g_off[M2];            // CSR offsets
__device__ int                g_list[M2];           // src rows grouped by dst

__device__ __forceinline__ unsigned sortable_f32(float f) {
    unsigned u = __float_as_uint(f);
    return (u & 0x80000000u) ? ~u : (u | 0x80000000u);
}

// ------------------------------------------------------------------------
// K1: metric = mean over heads of key_layer[0], L2-normalized per row.
//     Also initializes g_best.
// grid: 512 blocks x 256 threads (one warp per row)
// ------------------------------------------------------------------------
__global__ void k_metric(const float* __restrict__ key) {
    int gtid = blockIdx.x * blockDim.x + threadIdx.x;
    if (gtid < M2) g_best[gtid] = 0ull;

    int row  = gtid >> 5;                 // one warp per row
    int lane = threadIdx.x & 31;
    if (row < L_TOK) {
        float v0 = 0.f, v1 = 0.f;
        const float* base = key + (size_t)row * DH;
        #pragma unroll
        for (int h = 0; h < H_HEAD; h++) {
            v0 += base[(size_t)h * L_TOK * DH + lane];
            v1 += base[(size_t)h * L_TOK * DH + lane + 32];
        }
        const float invH = 1.0f / (float)H_HEAD;
        v0 *= invH; v1 *= invH;
        float ss = v0 * v0 + v1 * v1;
        #pragma unroll
        for (int o = 16; o; o >>= 1) ss += __shfl_xor_sync(0xffffffffu, ss, o);
        float r = rsqrtf(ss);
        r = r * (1.5f - 0.5f * ss * r * r);   // one Newton step
        g_m[row * DH + lane]      = v0 * r;
        g_m[row * DH + lane + 32] = v1 * r;
    }
}

// ------------------------------------------------------------------------
// K2: for every a-row i (even rows of m), argmax over b-rows j (odd rows)
//     of dot(a_i, b_j).  2048 x 2048 x 64 fp32 GEMM + argmax epilogue.
// Tile 64x64, 256 threads, 4x4 microtile, single K pass (K = 64).
// grid: (32, 32)
// ------------------------------------------------------------------------
#define TS 64
#define SSTR 68    // smem row stride in floats: 68*4 = 272 B, 16B aligned
__global__ __launch_bounds__(256) void k_argmax() {
    __shared__ float As[TS * SSTR];   // K-major: As[k*SSTR + m]
    __shared__ float Bs[TS * SSTR];

    int tid = threadIdx.x;
    int tx  = tid & 15;               // n direction, 0..15
    int ty  = tid >> 4;               // m direction, 0..15

    int aRow0 = blockIdx.y * TS;      // a-row tile base (in 0..2047)
    int bRow0 = blockIdx.x * TS;      // b-row tile base

    // Load tiles (transpose to K-major). lane-major over m keeps STS conflict-free.
    int lm = tid & 15;                // m within 16-row group
    int kq = tid >> 4;                // which float4 along K, 0..15
    #pragma unroll
    for (int it = 0; it < 4; it++) {
        int m = it * 16 + lm;
        float4 va = *(const float4*)&g_m[(size_t)(2 * (aRow0 + m)) * DH + kq * 4];
        float4 vb = *(const float4*)&g_m[(size_t)(2 * (bRow0 + m) + 1) * DH + kq * 4];
        As[(kq * 4 + 0) * SSTR + m] = va.x;
        As[(kq * 4 + 1) * SSTR + m] = va.y;
        As[(kq * 4 + 2) * SSTR + m] = va.z;
        As[(kq * 4 + 3) * SSTR + m] = va.w;
        Bs[(kq * 4 + 0) * SSTR + m] = vb.x;
        Bs[(kq * 4 + 1) * SSTR + m] = vb.y;
        Bs[(kq * 4 + 2) * SSTR + m] = vb.z;
        Bs[(kq * 4 + 3) * SSTR + m] = vb.w;
    }
    __syncthreads();

    float acc[4][4];
    #pragma unroll
    for (int r = 0; r < 4; r++)
        #pragma unroll
        for (int c = 0; c < 4; c++) acc[r][c] = 0.f;

    #pragma unroll 16
    for (int k = 0; k < TS; k++) {
        float4 av = *(const float4*)&As[k * SSTR + ty * 4];
        float4 bv = *(const float4*)&Bs[k * SSTR + tx * 4];
        float a[4] = {av.x, av.y, av.z, av.w};
        float b[4] = {bv.x, bv.y, bv.z, bv.w};
        #pragma unroll
        for (int r = 0; r < 4; r++)
            #pragma unroll
            for (int c = 0; c < 4; c++)
                acc[r][c] = fmaf(a[r], b[c], acc[r][c]);
    }

    // Argmax epilogue: per a-row, reduce across the 16 threads (one half-warp)
    #pragma unroll
    for (int r = 0; r < 4; r++) {
        int row = aRow0 + ty * 4 + r;
        unsigned long long key = 0ull;
        #pragma unroll
        for (int c = 0; c < 4; c++) {
            int col = bRow0 + tx * 4 + c;
            unsigned long long k2 =
                ((unsigned long long)sortable_f32(acc[r][c]) << 32) |
                (unsigned)(~(unsigned)col);   // smaller col wins ties
            key = (k2 > key) ? k2 : key;
        }
        #pragma unroll
        for (int o = 8; o; o >>= 1) {
            unsigned long long other = __shfl_down_sync(0xffffffffu, key, o, 16);
            key = (other > key) ? other : key;
        }
        if (tx == 0) atomicMax(&g_best[row], key);
    }
}

// ------------------------------------------------------------------------
// K3: build CSR (counts, offsets, src lists) from packed argmax results.
// Single block, 1024 threads (2 rows per thread).
// ------------------------------------------------------------------------
__global__ __launch_bounds__(1024) void k_build() {
    __shared__ int s_cnt[M2];
    __shared__ int s_off[M2];
    __shared__ int s_part[1024];
    int t = threadIdx.x;
    int i0 = 2 * t, i1 = 2 * t + 1;

    s_cnt[i0] = 0; s_cnt[i1] = 0;
    __syncthreads();

    int dA = (int)(~(unsigned)g_best[i0]) & (M2 - 1);
    int dB = (int)(~(unsigned)g_best[i1]) & (M2 - 1);
    if (i0 >= 1) atomicAdd(&s_cnt[dA], 1);   // src row 0 is unmerged
    atomicAdd(&s_cnt[dB], 1);
    __syncthreads();

    int a = s_cnt[i0], b = s_cnt[i1];
    int pair = a + b;
    s_part[t] = pair;
    __syncthreads();
    // Hillis-Steele inclusive scan over 1024 pair sums
    #pragma unroll
    for (int off = 1; off < 1024; off <<= 1) {
        int v = (t >= off) ? s_part[t - off] : 0;
        __syncthreads();
        s_part[t] += v;
        __syncthreads();
    }
    int excl = s_part[t] - pair;
    s_off[i0] = excl;
    s_off[i1] = excl + a;
    g_cnt[i0] = a;  g_cnt[i1] = b;
    g_off[i0] = excl; g_off[i1] = excl + a;
    __syncthreads();

    // reuse s_cnt as fill cursor
    s_cnt[i0] = s_off[i0]; s_cnt[i1] = s_off[i1];
    __syncthreads();
    if (i0 >= 1) { int p = atomicAdd(&s_cnt[dA], 1); g_list[p] = i0; }
    {             int p = atomicAdd(&s_cnt[dB], 1); g_list[p] = i1; }
}

// ------------------------------------------------------------------------
// K4: gather-merge. Block j < 2048: out row 1+j = (dst_row + sum srcs)/(1+cnt).
//     Block 2048: unmerged row 0 + attention mask + tome[0].
// grid: 2049 blocks x 192 threads (768 floats = 192 float4)
// ------------------------------------------------------------------------
__global__ __launch_bounds__(192) void k_merge(const float* __restrict__ hidden,
                                               const float* __restrict__ tome,
                                               float* __restrict__ out) {
    float* out_tok  = out;                              // 2049 x 768
    float* out_mask = out + (size_t)OUT_TOK * D_HID;    // 2049
    float* out_tome = out_mask + OUT_TOK;               // 2049
    int b = blockIdx.x, t = threadIdx.x;

    if (b == M2) {   // unmerged row 0, mask, tome[0]
        ((float4*)out_tok)[t] = ((const float4*)hidden)[t];
        for (int i = t; i < OUT_TOK; i += 192) out_mask[i] = 0.0f;
        if (t == 0) out_tome[0] = tome[0];
        return;
    }

    int j   = b;
    int cnt = g_cnt[j];
    int off = g_off[j];
    float inv = 1.0f / (1.0f + (float)cnt);

    float4 acc = ((const float4*)&hidden[(size_t)(2 * j + 1) * D_HID])[t];

    int s = 0;
    for (; s + 4 <= cnt; s += 4) {     // 4 independent in-flight rows
        int i0 = g_list[off + s + 0];
        int i1 = g_list[off + s + 1];
        int i2 = g_list[off + s + 2];
        int i3 = g_list[off + s + 3];
        float4 v0 = ((const float4*)&hidden[(size_t)(2 * i0) * D_HID])[t];
        float4 v1 = ((const float4*)&hidden[(size_t)(2 * i1) * D_HID])[t];
        float4 v2 = ((const float4*)&hidden[(size_t)(2 * i2) * D_HID])[t];
        float4 v3 = ((const float4*)&hidden[(size_t)(2 * i3) * D_HID])[t];
        acc.x += v0.x + v1.x + v2.x + v3.x;
        acc.y += v0.y + v1.y + v2.y + v3.y;
        acc.z += v0.z + v1.z + v2.z + v3.z;
        acc.w += v0.w + v1.w + v2.w + v3.w;
    }
    for (; s < cnt; s++) {
        int i0 = g_list[off + s];
        float4 v0 = ((const float4*)&hidden[(size_t)(2 * i0) * D_HID])[t];
        acc.x += v0.x; acc.y += v0.y; acc.z += v0.z; acc.w += v0.w;
    }
    acc.x *= inv; acc.y *= inv; acc.z *= inv; acc.w *= inv;
    ((float4*)&out_tok[(size_t)(1 + j) * D_HID])[t] = acc;

    if (t == 0) {
        float ts = tome[2 * j + 1];
        for (int q = 0; q < cnt; q++) ts += tome[2 * g_list[off + q]];
        out_tome[1 + j] = ts;
    }
}

// ------------------------------------------------------------------------
extern "C" void kernel_launch(void* const* d_in, const int* in_sizes, int n_in,
                              void* d_out, int out_size) {
    // inputs (metadata order): hidden_states, attention_mask,
    //                          self_attention_scores, key_layer, tome_size
    const float* hidden = (const float*)d_in[0];
    const float* key    = (const float*)d_in[3];
    const float* tome   = (const float*)d_in[4];
    float* out = (float*)d_out;

    k_metric<<<512, 256>>>(key);
    k_argmax<<<dim3(M2 / TS, M2 / TS), 256>>>();
    k_build<<<1, 1024>>>();
    k_merge<<<OUT_TOK, 192>>>(hidden, tome, out);
}